// round 15
// baseline (speedup 1.0000x reference)
#include <cuda_runtime.h>
#include <cuda_fp16.h>
#include <math.h>
#include <stdint.h>

#define SEQ 2048
#define HID 3584
#define NH 28
#define NKV 4
#define GRP 7
#define HD 128
#define SCALE_LG2  0.12751500885282288f     // (1/sqrt(128)) * log2(e)

// ---------------- scratch (static device globals; no runtime allocation) ----
__device__ __half g_hid_t[SEQ * HID];
__device__ __half g_wq_t[NH * HD * HID];
__device__ __half g_wk_t[NKV * HD * HID];
__device__ __half g_wv_t[NKV * HD * HID];
__device__ __half g_wo_t[HID * NH * HD];
__device__ __half g_qt[SEQ * NH * HD];       // rope(Q) fp16
__device__ __half g_kt[SEQ * NKV * HD];      // rope(K) fp16
__device__ __half g_vtT[NKV * HD * SEQ];     // V fp16 TRANSPOSED [h*d][s]
__device__ __half g_ot[SEQ * NH * HD];       // attn out fp16

// ---------------- helpers ----------------------------------------------------
__device__ __forceinline__ void mma_f16(float* c, const uint32_t* a, const uint32_t* b) {
    asm volatile(
        "mma.sync.aligned.m16n8k16.row.col.f32.f16.f16.f32 "
        "{%0,%1,%2,%3}, {%4,%5,%6,%7}, {%8,%9}, {%0,%1,%2,%3};"
        : "+f"(c[0]), "+f"(c[1]), "+f"(c[2]), "+f"(c[3])
        : "r"(a[0]), "r"(a[1]), "r"(a[2]), "r"(a[3]), "r"(b[0]), "r"(b[1]));
}
__device__ __forceinline__ void ldsm4(uint32_t* r, uint32_t addr) {
    asm volatile("ldmatrix.sync.aligned.m8n8.x4.shared.b16 {%0,%1,%2,%3}, [%4];"
        : "=r"(r[0]), "=r"(r[1]), "=r"(r[2]), "=r"(r[3]) : "r"(addr));
}
__device__ __forceinline__ uint32_t smem_u32(const void* p) {
    return (uint32_t)__cvta_generic_to_shared(p);
}
__device__ __forceinline__ void cp16(uint32_t s, const void* g) {
    asm volatile("cp.async.cg.shared.global [%0], [%1], 16;" :: "r"(s), "l"(g));
}
#define CP_COMMIT() asm volatile("cp.async.commit_group;" ::: "memory")
#define CP_WAIT(n)  asm volatile("cp.async.wait_group %0;" :: "n"(n) : "memory")

// ---------------- single fused fp32 -> fp16 converter ------------------------
#define CN0 ((long)SEQ * HID)
#define CN1 ((long)NH * HD * HID)
#define CN2 ((long)NKV * HD * HID)
#define CTOT (CN0 + CN1 + 2 * CN2 + CN1)

__global__ void conv_all(const float* __restrict__ h, const float* __restrict__ wq,
                         const float* __restrict__ wk, const float* __restrict__ wv,
                         const float* __restrict__ wo)
{
    long i = ((long)blockIdx.x * blockDim.x + threadIdx.x) * 8;
    const float* s; __half* d; long off;
    if (i < CN0)                       { s = h;  d = g_hid_t; off = i; }
    else if (i < CN0 + CN1)            { s = wq; d = g_wq_t;  off = i - CN0; }
    else if (i < CN0 + CN1 + CN2)      { s = wk; d = g_wk_t;  off = i - CN0 - CN1; }
    else if (i < CN0 + CN1 + 2 * CN2)  { s = wv; d = g_wv_t;  off = i - CN0 - CN1 - CN2; }
    else                               { s = wo; d = g_wo_t;  off = i - CN0 - CN1 - 2 * CN2; }
    float4 x = *(const float4*)(s + off);
    float4 y = *(const float4*)(s + off + 4);
    __half hh[8] = { __float2half_rn(x.x), __float2half_rn(x.y),
                     __float2half_rn(x.z), __float2half_rn(x.w),
                     __float2half_rn(y.x), __float2half_rn(y.y),
                     __float2half_rn(y.z), __float2half_rn(y.w) };
    *(uint4*)(d + off) = *(uint4*)hh;
}

// ---------------- FP16 tensor GEMM core: 128x256 block, warp 64x64 -----------
#define ASTRh 72
#define BSTRh 72
#define ASTAGE (128 * ASTRh)
#define BSTAGE (256 * BSTRh)
#define GEMM_SMEM ((3 * ASTAGE + 3 * BSTAGE) * 2)     // 165888 bytes
#define FS 258                                        // fp32 staging stride

__device__ __forceinline__ void gemm_core(
    const __half* __restrict__ A, const __half* __restrict__ B,
    int K, int bx, int by, __half* As, __half* Bs, float acc[32][4])
{
    const int tid  = threadIdx.x;
    const int warp = tid >> 5, lane = tid & 31;
    const int wm = (warp >> 2) * 64;          // 2 warp rows
    const int wn = (warp & 3) * 64;           // 4 warp cols
    const int arow = lane & 15, acol = (lane >> 4) << 3;
    const int brow = lane & 7, bk8 = ((lane >> 3) & 1) << 3;
    const int bnt  = lane >> 4;

#pragma unroll
    for (int i = 0; i < 32; i++)
#pragma unroll
        for (int j = 0; j < 4; j++) acc[i][j] = 0.f;

    const int T = K / 64;

#define LOAD_TILE(t_)                                                            \
    do {                                                                         \
        __half* ab_ = As + ((t_) % 3) * ASTAGE;                                  \
        __half* bb_ = Bs + ((t_) % 3) * BSTAGE;                                  \
        _Pragma("unroll")                                                        \
        for (int i_ = 0; i_ < 4; i_++) {                                         \
            int f_ = tid + i_ * 256;                                             \
            int row_ = f_ >> 3, ch_ = (f_ & 7) * 8;                              \
            cp16(smem_u32(ab_ + row_ * ASTRh + ch_),                             \
                 A + (size_t)(by * 128 + row_) * K + (t_) * 64 + ch_);           \
        }                                                                        \
        _Pragma("unroll")                                                        \
        for (int i_ = 0; i_ < 8; i_++) {                                         \
            int f_ = tid + i_ * 256;                                             \
            int row_ = f_ >> 3, ch_ = (f_ & 7) * 8;                              \
            cp16(smem_u32(bb_ + row_ * BSTRh + ch_),                             \
                 B + (size_t)(bx * 256 + row_) * K + (t_) * 64 + ch_);           \
        }                                                                        \
        CP_COMMIT();                                                             \
    } while (0)

    LOAD_TILE(0);
    LOAD_TILE(1);

    for (int t = 0; t < T; t++) {
        if (t < T - 1) CP_WAIT(1); else CP_WAIT(0);
        __syncthreads();

        if (t + 2 < T) LOAD_TILE(t + 2);

        const __half* as = As + (t % 3) * ASTAGE;
        const __half* bs = Bs + (t % 3) * BSTAGE;
#pragma unroll
        for (int kk = 0; kk < 64; kk += 16) {
            uint32_t a[4][4], bb4[4][4];
#pragma unroll
            for (int mt = 0; mt < 4; mt++)
                ldsm4(a[mt], smem_u32(as + (wm + mt * 16 + arow) * ASTRh + kk + acol));
#pragma unroll
            for (int np = 0; np < 4; np++)
                ldsm4(bb4[np], smem_u32(bs + (wn + (np * 2 + bnt) * 8 + brow) * BSTRh + kk + bk8));
#pragma unroll
            for (int mt = 0; mt < 4; mt++)
#pragma unroll
                for (int nt = 0; nt < 8; nt++)
                    mma_f16(acc[mt * 8 + nt], a[mt], &bb4[nt >> 1][(nt & 1) * 2]);
        }
    }
    __syncthreads();
#undef LOAD_TILE
}

// rope epilogue: stage fp32 + bias to smem, apply rope, write fp16 (Q or K)
// bias is the FULL bias vector; indexed with hbase*128 + local column.
template <int ISQ>
__device__ __forceinline__ void epi_rope(
    float acc[32][4], float* fs, const float* __restrict__ bias,
    const float* __restrict__ cosT, const float* __restrict__ sinT,
    int hbase, int by)
{
    const int tid = threadIdx.x;
    const int warp = tid >> 5, lane = tid & 31;
    const int g = lane >> 2, tg = lane & 3;
    const int wm = (warp >> 2) * 64, wn = (warp & 3) * 64;

#pragma unroll
    for (int mt = 0; mt < 4; mt++)
#pragma unroll
        for (int nt = 0; nt < 8; nt++) {
            int r0 = wm + mt * 16 + g;
            int c0 = wn + nt * 8 + 2 * tg;
            float b0 = bias[hbase * 128 + c0];
            float b1 = bias[hbase * 128 + c0 + 1];
            float* ca = acc[mt * 8 + nt];
            *(float2*)&fs[r0 * FS + c0]       = make_float2(ca[0] + b0, ca[1] + b1);
            *(float2*)&fs[(r0 + 8) * FS + c0] = make_float2(ca[2] + b0, ca[3] + b1);
        }
    __syncthreads();

    const int r = tid & 127, hg = tid >> 7;
    const int s = by * 128 + r;
    const int h = hbase + hg;
    __half* dst = ISQ ? (g_qt + ((size_t)s * NH + h) * HD)
                      : (g_kt + ((size_t)s * NKV + h) * HD);
#pragma unroll
    for (int d = 0; d < 64; d += 2) {
        float2 x0 = *(float2*)&fs[r * FS + hg * 128 + d];
        float2 x1 = *(float2*)&fs[r * FS + hg * 128 + d + 64];
        float2 c0 = *(const float2*)&cosT[s * HD + d];
        float2 s0 = *(const float2*)&sinT[s * HD + d];
        float2 c1 = *(const float2*)&cosT[s * HD + d + 64];
        float2 s1 = *(const float2*)&sinT[s * HD + d + 64];
        *(__half2*)(dst + d) =
            __floats2half2_rn(x0.x * c0.x - x1.x * s0.x, x0.y * c0.y - x1.y * s0.y);
        *(__half2*)(dst + d + 64) =
            __floats2half2_rn(x1.x * c1.x + x0.x * s1.x, x1.y * c1.y + x0.y * s1.y);
    }
    __syncthreads();
}

// Fused QKV: bx<14 -> Q(rope), 14-15 -> K(rope), 16-17 -> V(transposed fp16)
__global__ __launch_bounds__(256, 1) void gemm_qkv(
    const float* __restrict__ bq, const float* __restrict__ bk,
    const float* __restrict__ bv,
    const float* __restrict__ cosT, const float* __restrict__ sinT)
{
    extern __shared__ __align__(16) char gsm_raw[];
    __half* As = (__half*)gsm_raw;
    __half* Bs = As + 3 * ASTAGE;
    float* fs = (float*)gsm_raw;
    const int bx = blockIdx.x, by = blockIdx.y;
    float acc[32][4];

    if (bx < 14) {
        gemm_core(g_hid_t, g_wq_t, HID, bx, by, As, Bs, acc);
        epi_rope<1>(acc, fs, bq, cosT, sinT, bx * 2, by);
    } else if (bx < 16) {
        gemm_core(g_hid_t, g_wk_t + (size_t)(bx - 14) * 256 * HID, HID, 0, by, As, Bs, acc);
        epi_rope<0>(acc, fs, bk, cosT, sinT, (bx - 14) * 2, by);   // FIX: un-offset bk
    } else {
        gemm_core(g_hid_t, g_wv_t + (size_t)(bx - 16) * 256 * HID, HID, 0, by, As, Bs, acc);
        // V epilogue: transposed fp16 + bias
        const int tid = threadIdx.x;
        const int warp = tid >> 5, lane = tid & 31;
        const int g = lane >> 2, tg = lane & 3;
        const int wm = (warp >> 2) * 64, wn = (warp & 3) * 64;
#pragma unroll
        for (int mt = 0; mt < 4; mt++)
#pragma unroll
            for (int nt = 0; nt < 8; nt++) {
                int r0 = by * 128 + wm + mt * 16 + g;
                int c0 = (bx - 16) * 256 + wn + nt * 8 + 2 * tg;
                float b0 = bv[c0], b1 = bv[c0 + 1];
                float* ca = acc[mt * 8 + nt];
                g_vtT[(size_t)c0 * SEQ + r0]           = __float2half_rn(ca[0] + b0);
                g_vtT[(size_t)(c0 + 1) * SEQ + r0]     = __float2half_rn(ca[1] + b1);
                g_vtT[(size_t)c0 * SEQ + r0 + 8]       = __float2half_rn(ca[2] + b0);
                g_vtT[(size_t)(c0 + 1) * SEQ + r0 + 8] = __float2half_rn(ca[3] + b1);
            }
    }
}

__global__ __launch_bounds__(256, 1) void gemm_out(float* __restrict__ C)
{
    extern __shared__ __align__(16) char gsm_raw[];
    __half* As = (__half*)gsm_raw;
    __half* Bs = As + 3 * ASTAGE;
    const int bx = blockIdx.x, by = blockIdx.y;
    float acc[32][4];
    gemm_core(g_ot, g_wo_t, HID, bx, by, As, Bs, acc);

    const int tid = threadIdx.x;
    const int warp = tid >> 5, lane = tid & 31;
    const int g = lane >> 2, tg = lane & 3;
    const int wm = (warp >> 2) * 64, wn = (warp & 3) * 64;
#pragma unroll
    for (int mt = 0; mt < 4; mt++)
#pragma unroll
        for (int nt = 0; nt < 8; nt++) {
            int r0 = by * 128 + wm + mt * 16 + g;
            int c0 = bx * 256 + wn + nt * 8 + 2 * tg;
            float* ca = acc[mt * 8 + nt];
            *(float2*)(&C[(size_t)r0 * HID + c0])       = make_float2(ca[0], ca[1]);
            *(float2*)(&C[(size_t)(r0 + 8) * HID + c0]) = make_float2(ca[2], ca[3]);
        }
}

// ---------------- Flash attention (doc-aware tile skipping) ------------------
#define QSTRh 136
#define KSTRh 136
#define VTSTRh 72
#define PSTRh 72
#define KVTILEh (64 * KSTRh)
#define FLASH_SMEM ((128*QSTRh + 2*KVTILEh + 128*VTSTRh + 128*PSTRh) * 2 + 64 * 4)

__global__ __launch_bounds__(256) void flash_kernel(const int* __restrict__ doc)
{
    extern __shared__ __align__(16) __half fsm[];
    __half* Qs  = fsm;                        // [128][QSTRh]
    __half* Ks  = Qs + 128 * QSTRh;           // 2 x [64][KSTRh]
    __half* VTs = Ks + 2 * KVTILEh;           // [128 d][VTSTRh]
    __half* Ps  = VTs + 128 * VTSTRh;         // [128][PSTRh]
    int* kdoc = (int*)(Ps + 128 * PSTRh);

    const int qb = gridDim.x - 1 - blockIdx.x;
    const int head = blockIdx.y;
    const int kvh = head / GRP;
    const int q0 = qb * 128;
    const int tid = threadIdx.x;
    const int warp = tid >> 5, lane = tid & 31;
    const int g = lane >> 2, tg = lane & 3;
    const int m0 = warp * 16;
    const int arow = lane & 15, acol = (lane >> 4) << 3;
    const int brow = lane & 7, bk8 = ((lane >> 3) & 1) << 3;
    const int bnt  = lane >> 4;

    // doc-aware start tile
    const int dq_lo = __ldg(doc + q0), dq_hi = __ldg(doc + q0 + 127);
    int lo = 0, hi = q0;
    while (lo < hi) {
        int mid = (lo + hi) >> 1;
        if (__ldg(doc + mid) < dq_lo) lo = mid + 1; else hi = mid;
    }
    const int t0 = lo >> 6;
    const int tmax = 2 * qb + 1;
    const bool q_split = (dq_lo != dq_hi);

    for (int f = tid; f < 128 * 16; f += 256) {
        int row = f >> 4, c8 = (f & 15) * 8;
        cp16(smem_u32(Qs + row * QSTRh + c8),
             g_qt + ((size_t)(q0 + row) * NH + head) * HD + c8);
    }
    CP_COMMIT();
    for (int f = tid; f < 64 * 16; f += 256) {
        int row = f >> 4, c8 = (f & 15) * 8;
        cp16(smem_u32(Ks + row * KSTRh + c8),
             g_kt + ((size_t)(t0 * 64 + row) * NKV + kvh) * HD + c8);
    }
    CP_COMMIT();
    for (int f = tid; f < 128 * 8; f += 256) {
        int d = f >> 3, c8 = (f & 7) * 8;
        cp16(smem_u32(VTs + d * VTSTRh + c8),
             g_vtT + ((size_t)(kvh * HD + d)) * SEQ + t0 * 64 + c8);
    }
    CP_COMMIT();

    const int qr0 = q0 + m0 + g, qr1 = qr0 + 8;
    const int qd0 = __ldg(doc + qr0), qd1 = __ldg(doc + qr1);
    float mi0 = -1e30f, mi1 = -1e30f, li0 = 0.f, li1 = 0.f;
    float o[16][4];
#pragma unroll
    for (int i = 0; i < 16; i++)
#pragma unroll
        for (int j = 0; j < 4; j++) o[i][j] = 0.f;

    for (int t = t0; t <= tmax; t++) {
        const int k0 = t * 64;
        const int dk_lo = __ldg(doc + k0), dk_hi = __ldg(doc + k0 + 63);
        const bool need_mask = (t >= 2 * qb) | (dk_lo != dk_hi) |
                               (dk_lo != dq_lo) | q_split;
        if (need_mask && tid < 64) kdoc[tid] = doc[k0 + tid];
        CP_WAIT(1);
        __syncthreads();

        const __half* ks = Ks + (t & 1) * KVTILEh;

        float s[8][4];
#pragma unroll
        for (int i = 0; i < 8; i++)
#pragma unroll
            for (int j = 0; j < 4; j++) s[i][j] = 0.f;

#pragma unroll
        for (int kk = 0; kk < 128; kk += 16) {
            uint32_t a[4];
            ldsm4(a, smem_u32(Qs + (m0 + arow) * QSTRh + kk + acol));
#pragma unroll
            for (int np = 0; np < 4; np++) {
                uint32_t bb[4];
                ldsm4(bb, smem_u32(ks + ((np * 2 + bnt) * 8 + brow) * KSTRh + kk + bk8));
                mma_f16(s[np * 2 + 0], a, bb);
                mma_f16(s[np * 2 + 1], a, bb + 2);
            }
        }

        float mx0 = -1e30f, mx1 = -1e30f;
        if (need_mask) {
#pragma unroll
            for (int nt = 0; nt < 8; nt++) {
                int c0 = k0 + nt * 8 + 2 * tg;
                int d0 = kdoc[nt * 8 + 2 * tg];
                int d1 = kdoc[nt * 8 + 2 * tg + 1];
                s[nt][0] = (qr0 >= c0     && qd0 == d0) ? s[nt][0] * SCALE_LG2 : -1e30f;
                s[nt][1] = (qr0 >= c0 + 1 && qd0 == d1) ? s[nt][1] * SCALE_LG2 : -1e30f;
                s[nt][2] = (qr1 >= c0     && qd1 == d0) ? s[nt][2] * SCALE_LG2 : -1e30f;
                s[nt][3] = (qr1 >= c0 + 1 && qd1 == d1) ? s[nt][3] * SCALE_LG2 : -1e30f;
                mx0 = fmaxf(mx0, fmaxf(s[nt][0], s[nt][1]));
                mx1 = fmaxf(mx1, fmaxf(s[nt][2], s[nt][3]));
            }
        } else {
#pragma unroll
            for (int nt = 0; nt < 8; nt++) {
                s[nt][0] *= SCALE_LG2; s[nt][1] *= SCALE_LG2;
                s[nt][2] *= SCALE_LG2; s[nt][3] *= SCALE_LG2;
                mx0 = fmaxf(mx0, fmaxf(s[nt][0], s[nt][1]));
                mx1 = fmaxf(mx1, fmaxf(s[nt][2], s[nt][3]));
            }
        }
        mx0 = fmaxf(mx0, __shfl_xor_sync(0xffffffffu, mx0, 1));
        mx0 = fmaxf(mx0, __shfl_xor_sync(0xffffffffu, mx0, 2));
        mx1 = fmaxf(mx1, __shfl_xor_sync(0xffffffffu, mx1, 1));
        mx1 = fmaxf(mx1, __shfl_xor_sync(0xffffffffu, mx1, 2));

        float nm0 = fmaxf(mi0, mx0), nm1 = fmaxf(mi1, mx1);
        float cr0 = exp2f(mi0 - nm0), cr1 = exp2f(mi1 - nm1);
        mi0 = nm0; mi1 = nm1;
#pragma unroll
        for (int nt = 0; nt < 16; nt++) {
            o[nt][0] *= cr0; o[nt][1] *= cr0;
            o[nt][2] *= cr1; o[nt][3] *= cr1;
        }

        float rs0 = 0.f, rs1 = 0.f;
#pragma unroll
        for (int nt = 0; nt < 8; nt++) {
            float pe0 = (s[nt][0] > -1e29f) ? exp2f(s[nt][0] - nm0) : 0.f;
            float pe1 = (s[nt][1] > -1e29f) ? exp2f(s[nt][1] - nm0) : 0.f;
            float pe2 = (s[nt][2] > -1e29f) ? exp2f(s[nt][2] - nm1) : 0.f;
            float pe3 = (s[nt][3] > -1e29f) ? exp2f(s[nt][3] - nm1) : 0.f;
            rs0 += pe0 + pe1; rs1 += pe2 + pe3;
            int c = nt * 8 + 2 * tg;
            *(__half2*)(Ps + (m0 + g) * PSTRh + c)     = __floats2half2_rn(pe0, pe1);
            *(__half2*)(Ps + (m0 + 8 + g) * PSTRh + c) = __floats2half2_rn(pe2, pe3);
        }
        rs0 += __shfl_xor_sync(0xffffffffu, rs0, 1);
        rs0 += __shfl_xor_sync(0xffffffffu, rs0, 2);
        rs1 += __shfl_xor_sync(0xffffffffu, rs1, 1);
        rs1 += __shfl_xor_sync(0xffffffffu, rs1, 2);
        li0 = li0 * cr0 + rs0;
        li1 = li1 * cr1 + rs1;

        if (t < tmax) {
            const int kn = k0 + 64;
            __half* kd = Ks + ((t + 1) & 1) * KVTILEh;
            for (int f = tid; f < 64 * 16; f += 256) {
                int row = f >> 4, c8 = (f & 15) * 8;
                cp16(smem_u32(kd + row * KSTRh + c8),
                     g_kt + ((size_t)(kn + row) * NKV + kvh) * HD + c8);
            }
            CP_COMMIT();
            CP_WAIT(1);
        } else {
            CP_WAIT(0);
        }
        __syncthreads();

#pragma unroll
        for (int kk = 0; kk < 64; kk += 16) {
            uint32_t a[4];
            ldsm4(a, smem_u32(Ps + (m0 + arow) * PSTRh + kk + acol));
#pragma unroll
            for (int np = 0; np < 8; np++) {
                uint32_t bb[4];
                ldsm4(bb, smem_u32(VTs + ((np * 2 + bnt) * 8 + brow) * VTSTRh + kk + bk8));
                mma_f16(o[np * 2 + 0], a, bb);
                mma_f16(o[np * 2 + 1], a, bb + 2);
            }
        }
        __syncthreads();

        if (t < tmax) {
            const int kn = k0 + 64;
            for (int f = tid; f < 128 * 8; f += 256) {
                int d = f >> 3, c8 = (f & 7) * 8;
                cp16(smem_u32(VTs + d * VTSTRh + c8),
                     g_vtT + ((size_t)(kvh * HD + d)) * SEQ + kn + c8);
            }
            CP_COMMIT();
        }
    }

    float inv0 = 1.f / li0, inv1 = 1.f / li1;
#pragma unroll
    for (int nt = 0; nt < 16; nt++) {
        int c = nt * 8 + 2 * tg;
        size_t b0 = ((size_t)qr0 * NH + head) * HD + c;
        size_t b1 = ((size_t)qr1 * NH + head) * HD + c;
        *(__half2*)(g_ot + b0) = __floats2half2_rn(o[nt][0] * inv0, o[nt][1] * inv0);
        *(__half2*)(g_ot + b1) = __floats2half2_rn(o[nt][2] * inv1, o[nt][3] * inv1);
    }
}

// ---------------- launch -----------------------------------------------------
extern "C" void kernel_launch(void* const* d_in, const int* in_sizes, int n_in,
                              void* d_out, int out_size)
{
    const float* hidden = (const float*)d_in[0];
    const float* cosT   = (const float*)d_in[1];
    const float* sinT   = (const float*)d_in[2];
    const int*   doc    = (const int*)  d_in[3];
    const float* Wq = (const float*)d_in[5];
    const float* bq = (const float*)d_in[6];
    const float* Wk = (const float*)d_in[7];
    const float* bk = (const float*)d_in[8];
    const float* Wv = (const float*)d_in[9];
    const float* bv = (const float*)d_in[10];
    const float* Wo = (const float*)d_in[11];
    float* out = (float*)d_out;

    // 1) fused fp32 -> fp16 conversion (1 launch)
    conv_all<<<(int)(CTOT / 8 / 256), 256>>>(hidden, Wq, Wk, Wv, Wo);

    // 2) fused QKV projections with in-epilogue RoPE (Q/K) + V transpose
    cudaFuncSetAttribute(gemm_qkv, cudaFuncAttributeMaxDynamicSharedMemorySize, GEMM_SMEM);
    gemm_qkv<<<dim3(18, SEQ / 128), 256, GEMM_SMEM>>>(bq, bk, bv, cosT, sinT);

    // 3) flash attention (doc-aware tile skipping)
    cudaFuncSetAttribute(flash_kernel, cudaFuncAttributeMaxDynamicSharedMemorySize, FLASH_SMEM);
    flash_kernel<<<dim3(SEQ / 128, NH), 256, FLASH_SMEM>>>(doc);

    // 4) output projection
    cudaFuncSetAttribute(gemm_out, cudaFuncAttributeMaxDynamicSharedMemorySize, GEMM_SMEM);
    gemm_out<<<dim3(HID / 256, SEQ / 128), 256, GEMM_SMEM>>>(out);
}

// round 16
// speedup vs baseline: 1.0599x; 1.0599x over previous
#include <cuda_runtime.h>
#include <cuda_fp16.h>
#include <math.h>
#include <stdint.h>

#define SEQ 2048
#define HID 3584
#define NH 28
#define NKV 4
#define GRP 7
#define HD 128
#define SCALE_LG2  0.12751500885282288f     // (1/sqrt(128)) * log2(e)

// ---------------- scratch (static device globals; no runtime allocation) ----
__device__ __half g_hid_t[SEQ * HID];
__device__ __half g_wq_t[NH * HD * HID];
__device__ __half g_wk_t[NKV * HD * HID];
__device__ __half g_wv_t[NKV * HD * HID];
__device__ __half g_wo_t[HID * NH * HD];
__device__ __half g_qt[SEQ * NH * HD];       // rope(Q) fp16
__device__ __half g_kt[SEQ * NKV * HD];      // rope(K) fp16
__device__ __half g_vtT[NKV * HD * SEQ];     // V fp16 TRANSPOSED [h*d][s]
__device__ __half g_ot[SEQ * NH * HD];       // attn out fp16

// ---------------- helpers ----------------------------------------------------
__device__ __forceinline__ void mma_f16(float* c, const uint32_t* a, const uint32_t* b) {
    asm volatile(
        "mma.sync.aligned.m16n8k16.row.col.f32.f16.f16.f32 "
        "{%0,%1,%2,%3}, {%4,%5,%6,%7}, {%8,%9}, {%0,%1,%2,%3};"
        : "+f"(c[0]), "+f"(c[1]), "+f"(c[2]), "+f"(c[3])
        : "r"(a[0]), "r"(a[1]), "r"(a[2]), "r"(a[3]), "r"(b[0]), "r"(b[1]));
}
__device__ __forceinline__ void ldsm4(uint32_t* r, uint32_t addr) {
    asm volatile("ldmatrix.sync.aligned.m8n8.x4.shared.b16 {%0,%1,%2,%3}, [%4];"
        : "=r"(r[0]), "=r"(r[1]), "=r"(r[2]), "=r"(r[3]) : "r"(addr));
}
__device__ __forceinline__ uint32_t smem_u32(const void* p) {
    return (uint32_t)__cvta_generic_to_shared(p);
}
__device__ __forceinline__ void cp16(uint32_t s, const void* g) {
    asm volatile("cp.async.cg.shared.global [%0], [%1], 16;" :: "r"(s), "l"(g));
}
#define CP_COMMIT() asm volatile("cp.async.commit_group;" ::: "memory")
#define CP_WAIT(n)  asm volatile("cp.async.wait_group %0;" :: "n"(n) : "memory")

// ---------------- single fused fp32 -> fp16 converter ------------------------
#define CN0 ((long)SEQ * HID)
#define CN1 ((long)NH * HD * HID)
#define CN2 ((long)NKV * HD * HID)
#define CTOT (CN0 + CN1 + 2 * CN2 + CN1)

__global__ void conv_all(const float* __restrict__ h, const float* __restrict__ wq,
                         const float* __restrict__ wk, const float* __restrict__ wv,
                         const float* __restrict__ wo)
{
    long i = ((long)blockIdx.x * blockDim.x + threadIdx.x) * 8;
    const float* s; __half* d; long off;
    if (i < CN0)                       { s = h;  d = g_hid_t; off = i; }
    else if (i < CN0 + CN1)            { s = wq; d = g_wq_t;  off = i - CN0; }
    else if (i < CN0 + CN1 + CN2)      { s = wk; d = g_wk_t;  off = i - CN0 - CN1; }
    else if (i < CN0 + CN1 + 2 * CN2)  { s = wv; d = g_wv_t;  off = i - CN0 - CN1 - CN2; }
    else                               { s = wo; d = g_wo_t;  off = i - CN0 - CN1 - 2 * CN2; }
    float4 x = *(const float4*)(s + off);
    float4 y = *(const float4*)(s + off + 4);
    __half hh[8] = { __float2half_rn(x.x), __float2half_rn(x.y),
                     __float2half_rn(x.z), __float2half_rn(x.w),
                     __float2half_rn(y.x), __float2half_rn(y.y),
                     __float2half_rn(y.z), __float2half_rn(y.w) };
    *(uint4*)(d + off) = *(uint4*)hh;
}

// ---------------- FP16 tensor GEMM core: 128x128 block, warp 64x32 -----------
#define GSTRh 72
#define GSTAGEh (128 * GSTRh)
#define GEMM_SMEM (3 * GSTAGEh * 2 * 2)   // 110592 bytes -> 2 CTAs/SM
#define FS 132                            // fp32 staging stride (128 + 4)

__device__ __forceinline__ void gemm_core(
    const __half* __restrict__ A, const __half* __restrict__ B,
    int K, int bx, int by, __half* As, __half* Bs, float acc[16][4])
{
    const int tid  = threadIdx.x;
    const int warp = tid >> 5, lane = tid & 31;
    const int wm = (warp >> 2) * 64;
    const int wn = (warp & 3) * 32;
    const int arow = lane & 15, acol = (lane >> 4) << 3;
    const int brow = lane & 7, bk8 = ((lane >> 3) & 1) << 3;
    const int bnt  = lane >> 4;

#pragma unroll
    for (int i = 0; i < 16; i++)
#pragma unroll
        for (int j = 0; j < 4; j++) acc[i][j] = 0.f;

    const int T = K / 64;

#define LOAD_TILE(t_)                                                            \
    do {                                                                         \
        __half* ab_ = As + ((t_) % 3) * GSTAGEh;                                 \
        __half* bb_ = Bs + ((t_) % 3) * GSTAGEh;                                 \
        _Pragma("unroll")                                                        \
        for (int i_ = 0; i_ < 4; i_++) {                                         \
            int f_ = tid + i_ * 256;                                             \
            int row_ = f_ >> 3, ch_ = (f_ & 7) * 8;                              \
            cp16(smem_u32(ab_ + row_ * GSTRh + ch_),                             \
                 A + (size_t)(by * 128 + row_) * K + (t_) * 64 + ch_);           \
            cp16(smem_u32(bb_ + row_ * GSTRh + ch_),                             \
                 B + (size_t)(bx * 128 + row_) * K + (t_) * 64 + ch_);           \
        }                                                                        \
        CP_COMMIT();                                                             \
    } while (0)

    LOAD_TILE(0);
    LOAD_TILE(1);

    for (int t = 0; t < T; t++) {
        if (t < T - 1) CP_WAIT(1); else CP_WAIT(0);
        __syncthreads();

        if (t + 2 < T) LOAD_TILE(t + 2);

        const __half* as = As + (t % 3) * GSTAGEh;
        const __half* bs = Bs + (t % 3) * GSTAGEh;
#pragma unroll
        for (int kk = 0; kk < 64; kk += 16) {
            uint32_t a[4][4], bb[2][4];
#pragma unroll
            for (int mt = 0; mt < 4; mt++)
                ldsm4(a[mt], smem_u32(as + (wm + mt * 16 + arow) * GSTRh + kk + acol));
#pragma unroll
            for (int np = 0; np < 2; np++)
                ldsm4(bb[np], smem_u32(bs + (wn + (np * 2 + bnt) * 8 + brow) * GSTRh + kk + bk8));
#pragma unroll
            for (int mt = 0; mt < 4; mt++)
#pragma unroll
                for (int nt = 0; nt < 4; nt++)
                    mma_f16(acc[mt * 4 + nt], a[mt], &bb[nt >> 1][(nt & 1) * 2]);
        }
    }
    __syncthreads();   // all smem reads done; stages reusable as fp32 staging
#undef LOAD_TILE
}

// rope epilogue for a 128x128 tile = 128 seq rows x 1 full head.
// Stage acc+bias to fp32 smem, rope pairs (d, d+64), write fp16.
template <int ISQ>
__device__ __forceinline__ void epi_rope(
    float acc[16][4], float* fs, const float* __restrict__ bias,
    const float* __restrict__ cosT, const float* __restrict__ sinT,
    int head, int by)
{
    const int tid = threadIdx.x;
    const int warp = tid >> 5, lane = tid & 31;
    const int g = lane >> 2, tg = lane & 3;
    const int wm = (warp >> 2) * 64, wn = (warp & 3) * 32;

#pragma unroll
    for (int mt = 0; mt < 4; mt++)
#pragma unroll
        for (int nt = 0; nt < 4; nt++) {
            int r0 = wm + mt * 16 + g;
            int c0 = wn + nt * 8 + 2 * tg;
            float b0 = bias[head * 128 + c0];
            float b1 = bias[head * 128 + c0 + 1];
            float* ca = acc[mt * 4 + nt];
            *(float2*)&fs[r0 * FS + c0]       = make_float2(ca[0] + b0, ca[1] + b1);
            *(float2*)&fs[(r0 + 8) * FS + c0] = make_float2(ca[2] + b0, ca[3] + b1);
        }
    __syncthreads();

    const int r = tid & 127, half = tid >> 7;   // 2 threads per row, 32 dims each
    const int s = by * 128 + r;
    __half* dst = ISQ ? (g_qt + ((size_t)s * NH + head) * HD)
                      : (g_kt + ((size_t)s * NKV + head) * HD);
    const int d0 = half * 32;
#pragma unroll
    for (int j = 0; j < 32; j += 2) {
        int d = d0 + j;
        float2 x0 = *(float2*)&fs[r * FS + d];
        float2 x1 = *(float2*)&fs[r * FS + d + 64];
        float2 c0 = *(const float2*)&cosT[s * HD + d];
        float2 s0 = *(const float2*)&sinT[s * HD + d];
        float2 c1 = *(const float2*)&cosT[s * HD + d + 64];
        float2 s1 = *(const float2*)&sinT[s * HD + d + 64];
        *(__half2*)(dst + d) =
            __floats2half2_rn(x0.x * c0.x - x1.x * s0.x, x0.y * c0.y - x1.y * s0.y);
        *(__half2*)(dst + d + 64) =
            __floats2half2_rn(x1.x * c1.x + x0.x * s1.x, x1.y * c1.y + x0.y * s1.y);
    }
}

// Fused QKV: bx<28 -> Q(rope, head=bx), 28..31 -> K(rope), 32..35 -> V(transposed)
__global__ __launch_bounds__(256) void gemm_qkv(
    const float* __restrict__ bq, const float* __restrict__ bk,
    const float* __restrict__ bv,
    const float* __restrict__ cosT, const float* __restrict__ sinT)
{
    extern __shared__ __align__(16) char gsm_raw[];
    __half* As = (__half*)gsm_raw;
    __half* Bs = As + 3 * GSTAGEh;
    float* fs = (float*)gsm_raw;
    const int bx = blockIdx.x, by = blockIdx.y;
    float acc[16][4];

    if (bx < 28) {
        gemm_core(g_hid_t, g_wq_t, HID, bx, by, As, Bs, acc);
        epi_rope<1>(acc, fs, bq, cosT, sinT, bx, by);
    } else if (bx < 32) {
        gemm_core(g_hid_t, g_wk_t, HID, bx - 28, by, As, Bs, acc);
        epi_rope<0>(acc, fs, bk, cosT, sinT, bx - 28, by);
    } else {
        gemm_core(g_hid_t, g_wv_t, HID, bx - 32, by, As, Bs, acc);
        // V epilogue: transposed fp16 + bias
        const int tid = threadIdx.x;
        const int warp = tid >> 5, lane = tid & 31;
        const int g = lane >> 2, tg = lane & 3;
        const int wm = (warp >> 2) * 64, wn = (warp & 3) * 32;
#pragma unroll
        for (int mt = 0; mt < 4; mt++)
#pragma unroll
            for (int nt = 0; nt < 4; nt++) {
                int r0 = by * 128 + wm + mt * 16 + g;
                int c0 = (bx - 32) * 128 + wn + nt * 8 + 2 * tg;
                float b0 = bv[c0], b1 = bv[c0 + 1];
                float* ca = acc[mt * 4 + nt];
                g_vtT[(size_t)c0 * SEQ + r0]           = __float2half_rn(ca[0] + b0);
                g_vtT[(size_t)(c0 + 1) * SEQ + r0]     = __float2half_rn(ca[1] + b1);
                g_vtT[(size_t)c0 * SEQ + r0 + 8]       = __float2half_rn(ca[2] + b0);
                g_vtT[(size_t)(c0 + 1) * SEQ + r0 + 8] = __float2half_rn(ca[3] + b1);
            }
    }
}

__global__ __launch_bounds__(256) void gemm_out(float* __restrict__ C)
{
    extern __shared__ __align__(16) char gsm_raw[];
    __half* As = (__half*)gsm_raw;
    __half* Bs = As + 3 * GSTAGEh;
    const int bx = blockIdx.x, by = blockIdx.y;
    float acc[16][4];
    gemm_core(g_ot, g_wo_t, HID, bx, by, As, Bs, acc);

    const int tid = threadIdx.x;
    const int warp = tid >> 5, lane = tid & 31;
    const int g = lane >> 2, tg = lane & 3;
    const int wm = (warp >> 2) * 64, wn = (warp & 3) * 32;
#pragma unroll
    for (int mt = 0; mt < 4; mt++)
#pragma unroll
        for (int nt = 0; nt < 4; nt++) {
            int r0 = by * 128 + wm + mt * 16 + g;
            int c0 = bx * 128 + wn + nt * 8 + 2 * tg;
            float* ca = acc[mt * 4 + nt];
            *(float2*)(&C[(size_t)r0 * HID + c0])       = make_float2(ca[0], ca[1]);
            *(float2*)(&C[(size_t)(r0 + 8) * HID + c0]) = make_float2(ca[2], ca[3]);
        }
}

// ---------------- Flash attention (doc-aware tile skipping) ------------------
#define QSTRh 136
#define KSTRh 136
#define VTSTRh 72
#define PSTRh 72
#define KVTILEh (64 * KSTRh)
#define FLASH_SMEM ((128*QSTRh + 2*KVTILEh + 128*VTSTRh + 128*PSTRh) * 2 + 64 * 4)

__global__ __launch_bounds__(256) void flash_kernel(const int* __restrict__ doc)
{
    extern __shared__ __align__(16) __half fsm[];
    __half* Qs  = fsm;                        // [128][QSTRh]
    __half* Ks  = Qs + 128 * QSTRh;           // 2 x [64][KSTRh]
    __half* VTs = Ks + 2 * KVTILEh;           // [128 d][VTSTRh]
    __half* Ps  = VTs + 128 * VTSTRh;         // [128][PSTRh]
    int* kdoc = (int*)(Ps + 128 * PSTRh);

    const int qb = gridDim.x - 1 - blockIdx.x;
    const int head = blockIdx.y;
    const int kvh = head / GRP;
    const int q0 = qb * 128;
    const int tid = threadIdx.x;
    const int warp = tid >> 5, lane = tid & 31;
    const int g = lane >> 2, tg = lane & 3;
    const int m0 = warp * 16;
    const int arow = lane & 15, acol = (lane >> 4) << 3;
    const int brow = lane & 7, bk8 = ((lane >> 3) & 1) << 3;
    const int bnt  = lane >> 4;

    // doc-aware start tile
    const int dq_lo = __ldg(doc + q0), dq_hi = __ldg(doc + q0 + 127);
    int lo = 0, hi = q0;
    while (lo < hi) {
        int mid = (lo + hi) >> 1;
        if (__ldg(doc + mid) < dq_lo) lo = mid + 1; else hi = mid;
    }
    const int t0 = lo >> 6;
    const int tmax = 2 * qb + 1;
    const bool q_split = (dq_lo != dq_hi);

    for (int f = tid; f < 128 * 16; f += 256) {
        int row = f >> 4, c8 = (f & 15) * 8;
        cp16(smem_u32(Qs + row * QSTRh + c8),
             g_qt + ((size_t)(q0 + row) * NH + head) * HD + c8);
    }
    CP_COMMIT();
    for (int f = tid; f < 64 * 16; f += 256) {
        int row = f >> 4, c8 = (f & 15) * 8;
        cp16(smem_u32(Ks + row * KSTRh + c8),
             g_kt + ((size_t)(t0 * 64 + row) * NKV + kvh) * HD + c8);
    }
    CP_COMMIT();
    for (int f = tid; f < 128 * 8; f += 256) {
        int d = f >> 3, c8 = (f & 7) * 8;
        cp16(smem_u32(VTs + d * VTSTRh + c8),
             g_vtT + ((size_t)(kvh * HD + d)) * SEQ + t0 * 64 + c8);
    }
    CP_COMMIT();

    const int qr0 = q0 + m0 + g, qr1 = qr0 + 8;
    const int qd0 = __ldg(doc + qr0), qd1 = __ldg(doc + qr1);
    float mi0 = -1e30f, mi1 = -1e30f, li0 = 0.f, li1 = 0.f;
    float o[16][4];
#pragma unroll
    for (int i = 0; i < 16; i++)
#pragma unroll
        for (int j = 0; j < 4; j++) o[i][j] = 0.f;

    for (int t = t0; t <= tmax; t++) {
        const int k0 = t * 64;
        const int dk_lo = __ldg(doc + k0), dk_hi = __ldg(doc + k0 + 63);
        const bool need_mask = (t >= 2 * qb) | (dk_lo != dk_hi) |
                               (dk_lo != dq_lo) | q_split;
        if (need_mask && tid < 64) kdoc[tid] = doc[k0 + tid];
        CP_WAIT(1);
        __syncthreads();

        const __half* ks = Ks + (t & 1) * KVTILEh;

        float s[8][4];
#pragma unroll
        for (int i = 0; i < 8; i++)
#pragma unroll
            for (int j = 0; j < 4; j++) s[i][j] = 0.f;

#pragma unroll
        for (int kk = 0; kk < 128; kk += 16) {
            uint32_t a[4];
            ldsm4(a, smem_u32(Qs + (m0 + arow) * QSTRh + kk + acol));
#pragma unroll
            for (int np = 0; np < 4; np++) {
                uint32_t bb[4];
                ldsm4(bb, smem_u32(ks + ((np * 2 + bnt) * 8 + brow) * KSTRh + kk + bk8));
                mma_f16(s[np * 2 + 0], a, bb);
                mma_f16(s[np * 2 + 1], a, bb + 2);
            }
        }

        float mx0 = -1e30f, mx1 = -1e30f;
        if (need_mask) {
#pragma unroll
            for (int nt = 0; nt < 8; nt++) {
                int c0 = k0 + nt * 8 + 2 * tg;
                int d0 = kdoc[nt * 8 + 2 * tg];
                int d1 = kdoc[nt * 8 + 2 * tg + 1];
                s[nt][0] = (qr0 >= c0     && qd0 == d0) ? s[nt][0] * SCALE_LG2 : -1e30f;
                s[nt][1] = (qr0 >= c0 + 1 && qd0 == d1) ? s[nt][1] * SCALE_LG2 : -1e30f;
                s[nt][2] = (qr1 >= c0     && qd1 == d0) ? s[nt][2] * SCALE_LG2 : -1e30f;
                s[nt][3] = (qr1 >= c0 + 1 && qd1 == d1) ? s[nt][3] * SCALE_LG2 : -1e30f;
                mx0 = fmaxf(mx0, fmaxf(s[nt][0], s[nt][1]));
                mx1 = fmaxf(mx1, fmaxf(s[nt][2], s[nt][3]));
            }
        } else {
#pragma unroll
            for (int nt = 0; nt < 8; nt++) {
                s[nt][0] *= SCALE_LG2; s[nt][1] *= SCALE_LG2;
                s[nt][2] *= SCALE_LG2; s[nt][3] *= SCALE_LG2;
                mx0 = fmaxf(mx0, fmaxf(s[nt][0], s[nt][1]));
                mx1 = fmaxf(mx1, fmaxf(s[nt][2], s[nt][3]));
            }
        }
        mx0 = fmaxf(mx0, __shfl_xor_sync(0xffffffffu, mx0, 1));
        mx0 = fmaxf(mx0, __shfl_xor_sync(0xffffffffu, mx0, 2));
        mx1 = fmaxf(mx1, __shfl_xor_sync(0xffffffffu, mx1, 1));
        mx1 = fmaxf(mx1, __shfl_xor_sync(0xffffffffu, mx1, 2));

        float nm0 = fmaxf(mi0, mx0), nm1 = fmaxf(mi1, mx1);
        float cr0 = exp2f(mi0 - nm0), cr1 = exp2f(mi1 - nm1);
        mi0 = nm0; mi1 = nm1;
#pragma unroll
        for (int nt = 0; nt < 16; nt++) {
            o[nt][0] *= cr0; o[nt][1] *= cr0;
            o[nt][2] *= cr1; o[nt][3] *= cr1;
        }

        float rs0 = 0.f, rs1 = 0.f;
#pragma unroll
        for (int nt = 0; nt < 8; nt++) {
            float pe0 = (s[nt][0] > -1e29f) ? exp2f(s[nt][0] - nm0) : 0.f;
            float pe1 = (s[nt][1] > -1e29f) ? exp2f(s[nt][1] - nm0) : 0.f;
            float pe2 = (s[nt][2] > -1e29f) ? exp2f(s[nt][2] - nm1) : 0.f;
            float pe3 = (s[nt][3] > -1e29f) ? exp2f(s[nt][3] - nm1) : 0.f;
            rs0 += pe0 + pe1; rs1 += pe2 + pe3;
            int c = nt * 8 + 2 * tg;
            *(__half2*)(Ps + (m0 + g) * PSTRh + c)     = __floats2half2_rn(pe0, pe1);
            *(__half2*)(Ps + (m0 + 8 + g) * PSTRh + c) = __floats2half2_rn(pe2, pe3);
        }
        rs0 += __shfl_xor_sync(0xffffffffu, rs0, 1);
        rs0 += __shfl_xor_sync(0xffffffffu, rs0, 2);
        rs1 += __shfl_xor_sync(0xffffffffu, rs1, 1);
        rs1 += __shfl_xor_sync(0xffffffffu, rs1, 2);
        li0 = li0 * cr0 + rs0;
        li1 = li1 * cr1 + rs1;

        if (t < tmax) {
            const int kn = k0 + 64;
            __half* kd = Ks + ((t + 1) & 1) * KVTILEh;
            for (int f = tid; f < 64 * 16; f += 256) {
                int row = f >> 4, c8 = (f & 15) * 8;
                cp16(smem_u32(kd + row * KSTRh + c8),
                     g_kt + ((size_t)(kn + row) * NKV + kvh) * HD + c8);
            }
            CP_COMMIT();
            CP_WAIT(1);
        } else {
            CP_WAIT(0);
        }
        __syncthreads();

#pragma unroll
        for (int kk = 0; kk < 64; kk += 16) {
            uint32_t a[4];
            ldsm4(a, smem_u32(Ps + (m0 + arow) * PSTRh + kk + acol));
#pragma unroll
            for (int np = 0; np < 8; np++) {
                uint32_t bb[4];
                ldsm4(bb, smem_u32(VTs + ((np * 2 + bnt) * 8 + brow) * VTSTRh + kk + bk8));
                mma_f16(o[np * 2 + 0], a, bb);
                mma_f16(o[np * 2 + 1], a, bb + 2);
            }
        }
        __syncthreads();

        if (t < tmax) {
            const int kn = k0 + 64;
            for (int f = tid; f < 128 * 8; f += 256) {
                int d = f >> 3, c8 = (f & 7) * 8;
                cp16(smem_u32(VTs + d * VTSTRh + c8),
                     g_vtT + ((size_t)(kvh * HD + d)) * SEQ + kn + c8);
            }
            CP_COMMIT();
        }
    }

    float inv0 = 1.f / li0, inv1 = 1.f / li1;
#pragma unroll
    for (int nt = 0; nt < 16; nt++) {
        int c = nt * 8 + 2 * tg;
        size_t b0 = ((size_t)qr0 * NH + head) * HD + c;
        size_t b1 = ((size_t)qr1 * NH + head) * HD + c;
        *(__half2*)(g_ot + b0) = __floats2half2_rn(o[nt][0] * inv0, o[nt][1] * inv0);
        *(__half2*)(g_ot + b1) = __floats2half2_rn(o[nt][2] * inv1, o[nt][3] * inv1);
    }
}

// ---------------- launch -----------------------------------------------------
extern "C" void kernel_launch(void* const* d_in, const int* in_sizes, int n_in,
                              void* d_out, int out_size)
{
    const float* hidden = (const float*)d_in[0];
    const float* cosT   = (const float*)d_in[1];
    const float* sinT   = (const float*)d_in[2];
    const int*   doc    = (const int*)  d_in[3];
    const float* Wq = (const float*)d_in[5];
    const float* bq = (const float*)d_in[6];
    const float* Wk = (const float*)d_in[7];
    const float* bk = (const float*)d_in[8];
    const float* Wv = (const float*)d_in[9];
    const float* bv = (const float*)d_in[10];
    const float* Wo = (const float*)d_in[11];
    float* out = (float*)d_out;

    // 1) fused fp32 -> fp16 conversion (1 launch)
    conv_all<<<(int)(CTOT / 8 / 256), 256>>>(hidden, Wq, Wk, Wv, Wo);

    // 2) fused QKV projections with in-epilogue RoPE (Q/K) + V transpose
    cudaFuncSetAttribute(gemm_qkv, cudaFuncAttributeMaxDynamicSharedMemorySize, GEMM_SMEM);
    gemm_qkv<<<dim3(36, SEQ / 128), 256, GEMM_SMEM>>>(bq, bk, bv, cosT, sinT);

    // 3) flash attention (doc-aware tile skipping)
    cudaFuncSetAttribute(flash_kernel, cudaFuncAttributeMaxDynamicSharedMemorySize, FLASH_SMEM);
    flash_kernel<<<dim3(SEQ / 128, NH), 256, FLASH_SMEM>>>(doc);

    // 4) output projection
    cudaFuncSetAttribute(gemm_out, cudaFuncAttributeMaxDynamicSharedMemorySize, GEMM_SMEM);
    gemm_out<<<dim3(HID / 128, SEQ / 128), 256, GEMM_SMEM>>>(out);
}